// round 1
// baseline (speedup 1.0000x reference)
#include <cuda_runtime.h>

// Problem constants (fixed shapes from reference)
#define TT 4
#define BB 512
#define GG 16
#define NN 256      // GG*GG
#define DD 32
#define NPAD 257    // smem column padding -> conflict-free [d][n] access
#define NEG_BIG_F (-1e30f)

// Global accumulators: zwl, zpl, pl(=sum cos*w, negated later), ol, nobj
__device__ double g_acc[5];

__global__ void init_kernel() {
    if (threadIdx.x < 5) g_acc[threadIdx.x] = 0.0;
}

__global__ __launch_bounds__(256, 2) void losses_kernel(
    const float* __restrict__ z_what,
    const float* __restrict__ z_pres_prob,
    const float* __restrict__ z_pres)
{
    const int blk = blockIdx.x;
    const int t = blk >> 9;        // / BB (BB=512)
    const int b = blk & (BB - 1);
    const int tid = threadIdx.x;

    extern __shared__ float sm[];
    float* s_wa  = sm;                    // [DD][NPAD] raw z_what at t
    float* s_wb  = sm + DD * NPAD;        // [DD][NPAD] raw z_what at t+1
    float* s_pa  = sm + 2 * DD * NPAD;    // [NN] prob at t
    float* s_pb  = s_pa + NN;             // [NN] prob at t+1
    float* s_nb  = s_pb + NN;             // [NN] ||z_what[t+1][:,n]||
    float* s_red = s_nb + NN;             // 40 floats reduction scratch

    const size_t slice = (size_t)NN * DD; // 8192
    const float* ga = z_what + ((size_t)t * BB + b) * slice;
    const float* gb = ga + (size_t)BB * slice;

    // ---- Load both slices (float4, coalesced), transpose to d-major, fold zwl ----
    float zwl = 0.f;
    {
        const float4* ga4 = (const float4*)ga;
        const float4* gb4 = (const float4*)gb;
        #pragma unroll
        for (int it = 0; it < (NN * DD / 4) / 256; ++it) {  // 8 iters
            int k4 = it * 256 + tid;
            float4 va = ga4[k4];
            float4 vb = gb4[k4];
            int n  = k4 >> 3;          // 8 float4 per n (D=32)
            int d0 = (k4 & 7) * 4;
            float dx = vb.x - va.x, dy = vb.y - va.y, dz = vb.z - va.z, dw = vb.w - va.w;
            zwl += dx*dx + dy*dy + dz*dz + dw*dw;
            s_wa[(d0+0)*NPAD + n] = va.x;  s_wb[(d0+0)*NPAD + n] = vb.x;
            s_wa[(d0+1)*NPAD + n] = va.y;  s_wb[(d0+1)*NPAD + n] = vb.y;
            s_wa[(d0+2)*NPAD + n] = va.z;  s_wb[(d0+2)*NPAD + n] = vb.z;
            s_wa[(d0+3)*NPAD + n] = va.w;  s_wb[(d0+3)*NPAD + n] = vb.w;
        }
    }
    {
        const float* pa = z_pres_prob + ((size_t)t * BB + b) * NN;
        const float* pb = pa + (size_t)BB * NN;
        s_pa[tid] = pa[tid];
        s_pb[tid] = pb[tid];
    }
    __syncthreads();

    const int n = tid;            // one thread per grid cell, NN == blockDim.x
    const int i = n >> 4, j = n & 15;

    // ---- norms of z_what[t+1] columns ----
    float nb2 = 0.f;
    #pragma unroll
    for (int d = 0; d < DD; ++d) {
        float v = s_wb[d * NPAD + n];
        nb2 += v * v;
    }
    s_nb[n] = sqrtf(nb2);
    __syncthreads();

    // ---- z_pres loss (windows t=0,1 only) ----
    float zpl = 0.f;
    if (t < TT - 2) {
        const float* zp = z_pres + ((size_t)t * BB + b) * NN + n;
        float p0 = zp[0];
        float p1 = zp[(size_t)BB * NN];
        float p2 = zp[2 * (size_t)BB * NN];
        float sim = 1.f - (p2 - p0) * (p2 - p0);
        float del = (p2 - p1) * (p2 - p1) + (p0 - p1) * (p0 - p1);
        zpl = sim * del;
    }

    // ---- precompute neighbor tables (registers) ----
    int   mp[9];  float paw[9];   // pool: clamped idx, prob weight (0 if OOB)
    int   mo[9];  bool  pres[9];  // objects: wrapped idx, presence mask
    #pragma unroll
    for (int q = 0; q < 9; ++q) {
        int di = q / 3 - 1, dj = q % 3 - 1;
        int ii = i + di, jj = j + dj;
        bool ok = ((unsigned)ii < GG) && ((unsigned)jj < GG);
        int m = ok ? (ii * GG + jj) : n;
        mp[q]  = m;
        paw[q] = ok ? s_pa[m] : 0.f;   // OOB -> contributes 0 (values are >= 0)
        int wi = (ii + GG) & (GG - 1);
        int wj = (jj + GG) & (GG - 1);
        int mw = wi * GG + wj;
        mo[q]   = mw;
        pres[q] = s_pb[mw] > 0.5f;
    }

    // ---- pool loss: 3x3 maxpool of |wa|*pa vs |wb[n]|*pb[n], cosine over D ----
    float dot = 0.f, na2 = 0.f, nbw2 = 0.f;
    const float pbn = s_pb[n];
    #pragma unroll
    for (int d = 0; d < DD; ++d) {
        const float* ra = s_wa + d * NPAD;
        float am = 0.f;   // all candidates >= 0, center always valid
        #pragma unroll
        for (int q = 0; q < 9; ++q)
            am = fmaxf(am, fabsf(ra[mp[q]]) * paw[q]);
        float bv = fabsf(s_wb[d * NPAD + n]) * pbn;
        dot  += am * bv;
        na2  += am * am;
        nbw2 += bv * bv;
    }
    float denom = fmaxf(sqrtf(na2) * sqrtf(nbw2), 1e-6f);
    float cosim = dot / denom;
    float plp = cosim * 0.5f * (s_pa[n] + pbn);   // pool_loss = -sum(plp)

    // ---- objects loss: 9 wrapped-neighbor cosines of raw vectors ----
    float pr[DD];
    float pn2 = 0.f;
    #pragma unroll
    for (int d = 0; d < DD; ++d) {
        pr[d] = s_wa[d * NPAD + n];
        pn2 += pr[d] * pr[d];
    }
    float prior_n = sqrtf(pn2);

    float sum_sim = 0.f, max_sim = NEG_BIG_F;
    bool any = false;
    #pragma unroll
    for (int q = 0; q < 9; ++q) {
        if (pres[q]) {
            int m = mo[q];
            float dp = 0.f;
            #pragma unroll
            for (int d = 0; d < DD; ++d)
                dp += pr[d] * s_wb[d * NPAD + m];
            float s = dp / fmaxf(prior_n * s_nb[m], 1e-8f);
            sum_sim += s;
            max_sim = fmaxf(max_sim, s);
            any = true;
        }
    }
    bool detected = s_pa[n] > 0.5f;
    float olp  = (detected && any) ? (sum_sim - 5.f * max_sim) : 0.f;
    float nobj = detected ? 1.f : 0.f;

    // ---- block reduce (8 warps) + atomic accumulate ----
    float vals[5] = {zwl, zpl, plp, olp, nobj};
    #pragma unroll
    for (int k = 0; k < 5; ++k) {
        float v = vals[k];
        #pragma unroll
        for (int o = 16; o > 0; o >>= 1) v += __shfl_down_sync(0xffffffffu, v, o);
        vals[k] = v;
    }
    int lane = tid & 31, w = tid >> 5;
    if (lane == 0) {
        #pragma unroll
        for (int k = 0; k < 5; ++k) s_red[w * 5 + k] = vals[k];
    }
    __syncthreads();
    if (tid == 0) {
        #pragma unroll
        for (int k = 0; k < 5; ++k) {
            float s = 0.f;
            #pragma unroll
            for (int wq = 0; wq < 8; ++wq) s += s_red[wq * 5 + k];
            atomicAdd(&g_acc[k], (double)s);
        }
    }
}

__global__ void final_kernel(const float* __restrict__ base_losses,
                             const void* __restrict__ step_ptr,
                             float* __restrict__ out, int out_size)
{
    float zwl  = (float)g_acc[0];
    float zpl  = (float)g_acc[1];
    float pl   = -(float)g_acc[2];
    float ol   = (float)g_acc[3];
    float nobj = (float)g_acc[4];
    float bsum = base_losses[0] + base_losses[1] + base_losses[2] + base_losses[3];

    // Robust global_step read: int32 / int64-LE both give value in first word;
    // fall back to float reinterpret if value implausible.
    int iv = *(const int*)step_ptr;
    float gs = (iv >= 0 && iv < 1000000000) ? (float)iv : *(const float*)step_ptr;
    float scaling = fminf(1.f, gs / 300000.f);

    float loss = bsum + zwl * 10.f + zpl * 1.f + pl * 1.f + ol * scaling * 10.f;
    float res[6] = {loss, zwl, zpl, pl, ol, nobj};
    for (int k = 0; k < 6 && k < out_size; ++k) out[k] = res[k];
}

extern "C" void kernel_launch(void* const* d_in, const int* in_sizes, int n_in,
                              void* d_out, int out_size) {
    const float* z_what      = (const float*)d_in[0];
    const float* z_pres_prob = (const float*)d_in[1];
    const float* z_pres      = (const float*)d_in[2];
    const float* base_losses = (const float*)d_in[3];
    const void*  gstep       = d_in[4];

    const size_t SMEM = (size_t)(2 * DD * NPAD + 3 * NN + 64) * sizeof(float); // ~69 KB
    cudaFuncSetAttribute(losses_kernel, cudaFuncAttributeMaxDynamicSharedMemorySize, (int)SMEM);

    init_kernel<<<1, 32>>>();
    losses_kernel<<<(TT - 1) * BB, 256, SMEM>>>(z_what, z_pres_prob, z_pres);
    final_kernel<<<1, 1>>>(base_losses, gstep, (float*)d_out, out_size);
}